// round 6
// baseline (speedup 1.0000x reference)
#include <cuda_runtime.h>
#include <math.h>

#define BATCH 4
#define IN_H 1080
#define IN_W 1920
#define C1 10
#define PH 539
#define PW 959
#define C2 16
#define H2 537
#define W2 957
#define C3 32
#define H3 535
#define W3 955
#define NPIX (H3*W3)            // 510925
#define TOT (BATCH*NPIX)        // 2043700
#define TOPK 1024

// ---------------- scratch (static device memory; no allocations) ----------------
__device__ float g_pool[BATCH*C1*PH*PW];
__device__ float g_c2[BATCH*C2*H2*W2];
__device__ float g_pred[TOT*4];
__device__ __align__(16) unsigned long long g_keys[TOT];
__device__ unsigned int g_hist16[65536];
__device__ unsigned long long g_prefix;
__device__ int g_remaining;
__device__ unsigned long long g_top[TOPK];
__device__ int g_topcnt;
__device__ float4 g_boxo[TOPK];
__device__ int g_valid[TOPK];
__device__ unsigned int g_nmsmask[TOPK*32];

// ---------------- conv1 (3->10, 3x3) + PReLU + 2x2 maxpool ----------------
// Reduction order: ky -> kx -> ci (ci innermost), FMA chain, bias added at END.
__global__ __launch_bounds__(256,2) void k_conv1pool(
    const float* __restrict__ x, const float* __restrict__ w,
    const float* __restrict__ bias, const float* __restrict__ alpha)
{
    __shared__ __align__(16) float s_in[3*18*66];
    __shared__ __align__(16) float s_w[27*12];
    __shared__ float s_b[C1], s_a[C1];
    const int tx = threadIdx.x, ty = threadIdx.y;
    const int tid = ty*32 + tx;
    const int b = blockIdx.z;
    const int px0 = blockIdx.x*32, py0 = blockIdx.y*8;
    const int ix0 = px0*2, iy0 = py0*2;

    for (int i = tid; i < 270; i += 256) {
        int st = i/10, co = i%10;
        int ci = st % 3; int r = st / 3; int ky = r/3, kx = r%3;
        s_w[st*12+co] = w[co*27 + ci*9 + ky*3 + kx];
    }
    if (tid < C1) { s_b[tid]=bias[tid]; s_a[tid]=alpha[tid]; }
    for (int i = tid; i < 3*18*66; i += 256) {
        int c = i/(18*66); int r = (i/66)%18; int cc = i%66;
        int gy = iy0 + r, gx = ix0 + cc;
        float v = 0.f;
        if (gy < IN_H && gx < IN_W) v = x[((b*3 + c)*IN_H + gy)*IN_W + gx];
        s_in[i] = v;
    }
    __syncthreads();
    const int px = px0 + tx, py = py0 + ty;
    if (px >= PW || py >= PH) return;

    float acc[4][C1];
    #pragma unroll
    for (int p=0;p<4;p++)
      #pragma unroll
      for (int co=0;co<C1;co++) acc[p][co] = 0.f;

    #pragma unroll
    for (int ky=0;ky<3;ky++){
      #pragma unroll
      for (int kx=0;kx<3;kx++){
        #pragma unroll
        for (int ci=0;ci<3;ci++){
          const int st = (ky*3+kx)*3+ci;
          const float4 wa = *(const float4*)&s_w[st*12];
          const float4 wb = *(const float4*)&s_w[st*12+4];
          const float2 wc = *(const float2*)&s_w[st*12+8];
          const float wv[10] = {wa.x,wa.y,wa.z,wa.w, wb.x,wb.y,wb.z,wb.w, wc.x,wc.y};
          float v[4];
          #pragma unroll
          for (int pyi=0;pyi<2;pyi++)
            #pragma unroll
            for (int pxi=0;pxi<2;pxi++)
              v[pyi*2+pxi] = s_in[ci*(18*66) + (2*ty+pyi+ky)*66 + (2*tx+pxi+kx)];
          #pragma unroll
          for (int p=0;p<4;p++)
            #pragma unroll
            for (int co=0;co<C1;co++)
              acc[p][co] = __fmaf_rn(v[p], wv[co], acc[p][co]);
        }
      }
    }
    #pragma unroll
    for (int co=0;co<C1;co++){
      float m = -1e30f;
      #pragma unroll
      for (int p=0;p<4;p++){
        float t = acc[p][co] + s_b[co];
        t = (t >= 0.f) ? t : s_a[co]*t;
        m = fmaxf(m, t);
      }
      g_pool[((b*C1+co)*PH+py)*PW+px] = m;
    }
}

// ---------------- conv2 (10->16, 3x3) + PReLU ----------------
#define S2_IN (10*18*66)   // 11880
#define S2_W  (90*16)      // 1440
__global__ __launch_bounds__(256,2) void k_conv2(
    const float* __restrict__ w, const float* __restrict__ bias, const float* __restrict__ alpha)
{
    extern __shared__ float sm2[];
    float* s_in = sm2;
    float* s_w  = sm2 + S2_IN;
    float* s_b  = s_w + S2_W;
    float* s_a  = s_b + C2;
    const int tx = threadIdx.x, ty = threadIdx.y;
    const int tid = ty*32+tx;
    const int b = blockIdx.z;
    const int ox0 = blockIdx.x*64, oy0 = blockIdx.y*16;

    for (int i = tid; i < S2_W; i += 256){
        int st=i/16, co=i%16;
        int ci = st % 10; int r = st / 10; int ky = r/3, kx = r%3;
        s_w[i] = w[co*90 + ci*9 + ky*3 + kx];
    }
    if (tid < C2){ s_b[tid]=bias[tid]; s_a[tid]=alpha[tid]; }
    for (int i = tid; i < S2_IN; i += 256){
        int ci = i/(18*66); int r=(i/66)%18; int cc=i%66;
        int gy=oy0+r, gx=ox0+cc;
        float v=0.f;
        if (gy<PH && gx<PW) v = g_pool[((b*C1+ci)*PH+gy)*PW+gx];
        s_in[i]=v;
    }
    __syncthreads();

    float acc[4][C2];
    #pragma unroll
    for (int p=0;p<4;p++)
      #pragma unroll
      for (int co=0;co<C2;co++) acc[p][co]=0.f;

    #pragma unroll
    for (int ky=0;ky<3;ky++){
      #pragma unroll
      for (int kx=0;kx<3;kx++){
        #pragma unroll 1
        for (int ci=0;ci<C1;ci++){
          const int st = (ky*3+kx)*10+ci;
          const float4 w0 = *(const float4*)&s_w[st*16];
          const float4 w1 = *(const float4*)&s_w[st*16+4];
          const float4 w2 = *(const float4*)&s_w[st*16+8];
          const float4 w3 = *(const float4*)&s_w[st*16+12];
          const float wv[16] = {w0.x,w0.y,w0.z,w0.w, w1.x,w1.y,w1.z,w1.w,
                                w2.x,w2.y,w2.z,w2.w, w3.x,w3.y,w3.z,w3.w};
          float v[4];
          #pragma unroll
          for (int pyi=0;pyi<2;pyi++)
            #pragma unroll
            for (int pxi=0;pxi<2;pxi++)
              v[pyi*2+pxi] = s_in[ci*(18*66) + (ty+8*pyi+ky)*66 + (tx+32*pxi+kx)];
          #pragma unroll
          for (int p=0;p<4;p++)
            #pragma unroll
            for (int co=0;co<C2;co++)
              acc[p][co] = __fmaf_rn(v[p], wv[co], acc[p][co]);
        }
      }
    }
    #pragma unroll
    for (int pyi=0;pyi<2;pyi++){
      int oy = oy0 + ty + 8*pyi;
      #pragma unroll
      for (int pxi=0;pxi<2;pxi++){
        int ox = ox0 + tx + 32*pxi;
        if (oy < H2 && ox < W2){
          int p = pyi*2+pxi;
          #pragma unroll
          for (int co=0;co<C2;co++){
            float t = acc[p][co] + s_b[co];
            t = (t>=0.f) ? t : s_a[co]*t;
            g_c2[((b*C2+co)*H2+oy)*W2+ox] = t;
          }
        }
      }
    }
}

// ------- conv3 (16->32, 3x3) + PReLU + 1x1 heads + softmax + key emit -------
#define S3_IN (16*10*66)   // 10560
#define S3_W  (144*32)     // 4608
__global__ __launch_bounds__(256,2) void k_conv3fused(
    const float* __restrict__ w3, const float* __restrict__ b3, const float* __restrict__ a3,
    const float* __restrict__ w41, const float* __restrict__ b41,
    const float* __restrict__ w42, const float* __restrict__ b42)
{
    extern __shared__ float sm3[];
    float* s_in  = sm3;
    float* s_w   = sm3 + S3_IN;
    float* s_b   = s_w + S3_W;     // 32
    float* s_a   = s_b + 32;       // 32
    float* s_w41 = s_a + 32;       // 64
    float* s_w42 = s_w41 + 64;     // 128
    float* s_b4  = s_w42 + 128;    // 8
    const int tx=threadIdx.x, ty=threadIdx.y, tid=ty*32+tx;
    const int b = blockIdx.z;
    const int ox0 = blockIdx.x*64, oy0 = blockIdx.y*8;

    for (int i=tid;i<S3_W;i+=256){
        int st=i/32, co=i%32;
        int ci = st % 16; int r = st / 16; int ky = r/3, kx = r%3;
        s_w[i] = w3[co*144 + ci*9 + ky*3 + kx];
    }
    if (tid<32){ s_b[tid]=b3[tid]; s_a[tid]=a3[tid]; }
    if (tid<64)  s_w41[tid]=w41[tid];
    if (tid<128) s_w42[tid]=w42[tid];
    if (tid<2)   s_b4[tid]=b41[tid];
    if (tid>=4 && tid<8) s_b4[tid-2]=b42[tid-4];
    for (int i=tid;i<S3_IN;i+=256){
        int ci=i/(10*66); int r=(i/66)%10; int cc=i%66;
        int gy=oy0+r, gx=ox0+cc;
        float v=0.f;
        if (gy<H2 && gx<W2) v = g_c2[((b*C2+ci)*H2+gy)*W2+gx];
        s_in[i]=v;
    }
    __syncthreads();

    float acc[2][C3];
    #pragma unroll
    for (int co=0;co<C3;co++){ acc[0][co]=0.f; acc[1][co]=0.f; }

    #pragma unroll
    for (int ky=0;ky<3;ky++){
      #pragma unroll
      for (int kx=0;kx<3;kx++){
        #pragma unroll 1
        for (int ci=0;ci<16;ci++){
          const int st = (ky*3+kx)*16+ci;
          float wv[32];
          #pragma unroll
          for (int q=0;q<8;q++){
            float4 t4 = *(const float4*)&s_w[st*32 + q*4];
            wv[q*4]=t4.x; wv[q*4+1]=t4.y; wv[q*4+2]=t4.z; wv[q*4+3]=t4.w;
          }
          const float v0 = s_in[ci*660 + (ty+ky)*66 + (tx+kx)];
          const float v1 = s_in[ci*660 + (ty+ky)*66 + (tx+32+kx)];
          #pragma unroll
          for (int co=0;co<32;co++){
            acc[0][co] = __fmaf_rn(v0, wv[co], acc[0][co]);
            acc[1][co] = __fmaf_rn(v1, wv[co], acc[1][co]);
          }
        }
      }
    }

    const int oy = oy0 + ty;
    #pragma unroll
    for (int p=0;p<2;p++){
      const int ox = ox0 + tx + 32*p;
      if (oy < H3 && ox < W3){
        float l0 = 0.f, l1 = 0.f;
        float pr0=0.f, pr1=0.f, pr2=0.f, pr3=0.f;
        #pragma unroll
        for (int co=0;co<32;co++){
          float h = acc[p][co] + s_b[co];
          h = (h>=0.f) ? h : s_a[co]*h;
          l0  = __fmaf_rn(h, s_w41[co],     l0);
          l1  = __fmaf_rn(h, s_w41[32+co],  l1);
          pr0 = __fmaf_rn(h, s_w42[co],     pr0);
          pr1 = __fmaf_rn(h, s_w42[32+co],  pr1);
          pr2 = __fmaf_rn(h, s_w42[64+co],  pr2);
          pr3 = __fmaf_rn(h, s_w42[96+co],  pr3);
        }
        l0 += s_b4[0]; l1 += s_b4[1];
        pr0 += s_b4[2]; pr1 += s_b4[3]; pr2 += s_b4[4]; pr3 += s_b4[5];
        float m  = fmaxf(l0,l1);
        float e0 = expf(l0-m), e1 = expf(l1-m);
        float score = __fdiv_rn(e1, __fadd_rn(e0,e1));
        int gidx = b*NPIX + oy*W3 + ox;
        unsigned long long key;
        if (score >= 0.6f){
          unsigned u = __float_as_uint(score) | 0x80000000u;
          key = ((unsigned long long)u << 32) | (unsigned long long)(0xFFFFFFFFu - (unsigned)gidx);
        } else {
          key = (unsigned long long)(unsigned)gidx;
        }
        g_keys[gidx] = key;
        g_pred[gidx*4+0]=pr0; g_pred[gidx*4+1]=pr1; g_pred[gidx*4+2]=pr2; g_pred[gidx*4+3]=pr3;
      }
    }
}

// ---------------- exact top-K: 4-pass 16-bit MSB radix select ----------------
__global__ void k_reset16(){
    g_hist16[blockIdx.x*1024+threadIdx.x]=0u;
    if (blockIdx.x==0 && threadIdx.x==0){ g_prefix=0ULL; g_remaining=TOPK; g_topcnt=0; }
}

__global__ void k_hist16(int p){
    int t = blockIdx.x*blockDim.x + threadIdx.x;
    int stride = gridDim.x*blockDim.x;
    unsigned long long pref = g_prefix;
    int shd = 48 - 16*p;
    const ulonglong2* keys2 = (const ulonglong2*)g_keys;
    for (int i = t; i < TOT/2; i += stride){
        ulonglong2 kk = keys2[i];
        bool ok0 = (p==0) || ((kk.x >> (64-16*p)) == pref);
        bool ok1 = (p==0) || ((kk.y >> (64-16*p)) == pref);
        if (ok0) atomicAdd(&g_hist16[(unsigned)(kk.x>>shd)&0xFFFFu], 1u);
        if (ok1) atomicAdd(&g_hist16[(unsigned)(kk.y>>shd)&0xFFFFu], 1u);
    }
}

__global__ void k_pick16(){   // <<<1,1024>>>
    __shared__ unsigned int ssum[1024];
    int t = threadIdx.x;
    unsigned base = (unsigned)t*64u;
    unsigned s = 0;
    #pragma unroll 8
    for (int i=0;i<64;i++) s += g_hist16[base+i];
    ssum[t] = s;
    __syncthreads();
    // inclusive suffix scan (Hillis-Steele)
    for (int off=1; off<1024; off<<=1){
        unsigned v = (t+off<1024) ? ssum[t+off] : 0u;
        __syncthreads();
        ssum[t] += v;
        __syncthreads();
    }
    unsigned r = (unsigned)g_remaining;
    unsigned above = (t<1023) ? ssum[t+1] : 0u;
    if (above < r && above + s >= r){
        unsigned c = above;
        for (int i=63;i>=0;i--){
            unsigned h = g_hist16[base+i];
            if (c + h >= r){
                g_prefix = (g_prefix<<16) | (unsigned long long)(base+(unsigned)i);
                g_remaining = (int)(r - c);
                break;
            }
            c += h;
        }
    }
    #pragma unroll 8
    for (int i=0;i<64;i++) g_hist16[base+i]=0u;
}

__global__ void k_compact(){
    unsigned long long T = g_prefix;   // exact 1024th-largest key
    int t = blockIdx.x*blockDim.x + threadIdx.x;
    int stride = gridDim.x*blockDim.x;
    const ulonglong2* keys2 = (const ulonglong2*)g_keys;
    for (int i = t; i < TOT/2; i += stride){
        ulonglong2 kk = keys2[i];
        if (kk.x >= T){
            int pos = atomicAdd(&g_topcnt, 1);
            if (pos < TOPK) g_top[pos] = kk.x;
        }
        if (kk.y >= T){
            int pos = atomicAdd(&g_topcnt, 1);
            if (pos < TOPK) g_top[pos] = kk.y;
        }
    }
}

// ---------------- bitonic sort (desc) + box decode ----------------
__global__ void k_sort(){
    __shared__ unsigned long long sk[TOPK];
    int t = threadIdx.x;
    sk[t] = g_top[t];
    for (int size=2; size<=TOPK; size<<=1){
      for (int stride=size>>1; stride>0; stride>>=1){
        __syncthreads();
        int j = t ^ stride;
        if (j > t){
          unsigned long long a = sk[t], c = sk[j];
          bool desc = ((t & size) == 0);
          bool sw = desc ? (a < c) : (a > c);
          if (sw){ sk[t]=c; sk[j]=a; }
        }
      }
    }
    __syncthreads();
    unsigned long long key = sk[t];
    g_top[t] = key;
    int valid = (key >> 32) != 0ULL;
    int idx = valid ? (int)(0xFFFFFFFFu - (unsigned)(key & 0xFFFFFFFFULL)) : 0;
    int bb = idx / NPIX; int rem = idx - bb*NPIX;
    int oy = rem / W3;   int ox = rem - oy*W3;
    float off = valid ? 100000.f * (float)bb : 0.f;
    float4 box;
    box.x = (float)(2*ox+1)  + off;
    box.y = (float)(2*oy+1)  + off;
    box.z = (float)(2*ox+12) + off;
    box.w = (float)(2*oy+12) + off;
    g_boxo[t]  = box;
    g_valid[t] = valid;
}

// ---------------- pairwise suppression bits ----------------
__global__ void k_mask(){
    int tid = blockIdx.x*blockDim.x + threadIdx.x;
    int i = tid >> 5;
    int w = tid & 31;
    if (i >= TOPK) return;
    float4 bi = g_boxo[i];
    float ai = (bi.z-bi.x)*(bi.w-bi.y);
    unsigned m = 0u;
    #pragma unroll 4
    for (int t2=0;t2<32;t2++){
        int j = w*32 + t2;
        float4 bj = g_boxo[j];
        float aj = (bj.z-bj.x)*(bj.w-bj.y);
        float xx1=fmaxf(bi.x,bj.x), yy1=fmaxf(bi.y,bj.y);
        float xx2=fminf(bi.z,bj.z), yy2=fminf(bi.w,bj.w);
        float inter = fmaxf(xx2-xx1,0.f)*fmaxf(yy2-yy1,0.f);
        float iou = __fdiv_rn(inter, ai+aj-inter);
        if (j > i && iou > 0.5f) m |= (1u<<t2);
    }
    g_nmsmask[i*32+w] = m;
}

// ---------------- sequential greedy NMS + refine + output ----------------
__global__ void k_final(float* __restrict__ out){
    extern __shared__ unsigned int smm[];     // TOPK*32 words
    __shared__ unsigned int s_keepw[32];
    int t = threadIdx.x;
    for (int i=t; i<TOPK*32; i+=TOPK) smm[i] = g_nmsmask[i];
    __syncthreads();
    if (t < 32){
        unsigned vword = 0u;
        for (int q=0;q<32;q++) vword |= (g_valid[t*32+q] ? 1u:0u) << q;
        unsigned sup = 0u, keepw = 0u;
        for (int i=0;i<TOPK;i++){
            int l = i >> 5, bb = i & 31;
            unsigned sw = __shfl_sync(0xffffffffu, sup,   l);
            unsigned vw = __shfl_sync(0xffffffffu, vword, l);
            bool keep = !((sw >> bb) & 1u) && ((vw >> bb) & 1u);
            if (keep) sup |= smm[i*32 + t];
            if (t == l) keepw |= ((unsigned)keep) << bb;
        }
        s_keepw[t] = keepw;
    }
    __syncthreads();
    bool keep = (s_keepw[t>>5] >> (t&31)) & 1u;
    float o0=0.f,o1=0.f,o2=0.f,o3=0.f,o4=0.f;
    if (keep){
        unsigned long long key = g_top[t];
        unsigned u = (unsigned)(key>>32);
        float score = __uint_as_float(u & 0x7FFFFFFFu);
        int idx = (int)(0xFFFFFFFFu - (unsigned)(key & 0xFFFFFFFFULL));
        int rem = idx % NPIX;
        int oy = rem / W3; int ox = rem - oy*W3;
        float x1 = (float)(2*ox+1),  y1 = (float)(2*oy+1);
        float x2 = (float)(2*ox+12), y2 = (float)(2*oy+12);
        float bw = x2-x1, bh = y2-y1;
        float p0 = g_pred[idx*4+0], p1=g_pred[idx*4+1], p2=g_pred[idx*4+2], p3=g_pred[idx*4+3];
        float r0 = x1 + p0*bw;
        float r1 = y1 + p1*bh;
        float r2 = x2 + p2*bw;
        float r3 = y2 + p3*bh;
        float rw = r2-r0, rh = r3-r1;
        float L = fmaxf(rw, rh);
        float nx1 = r0 + 0.5f*rw - 0.5f*L;
        float ny1 = r1 + 0.5f*rh - 0.5f*L;
        o0=nx1; o1=ny1; o2=nx1+L; o3=ny1+L; o4=score;
    }
    out[t*5+0]=o0; out[t*5+1]=o1; out[t*5+2]=o2; out[t*5+3]=o3; out[t*5+4]=o4;
}

// ---------------- launch ----------------
extern "C" void kernel_launch(void* const* d_in, const int* in_sizes, int n_in,
                              void* d_out, int out_size){
    const float* x   = (const float*)d_in[0];
    const float* w1  = (const float*)d_in[1];
    const float* b1  = (const float*)d_in[2];
    const float* a1  = (const float*)d_in[3];
    const float* w2  = (const float*)d_in[4];
    const float* b2  = (const float*)d_in[5];
    const float* a2  = (const float*)d_in[6];
    const float* w3  = (const float*)d_in[7];
    const float* b3  = (const float*)d_in[8];
    const float* a3  = (const float*)d_in[9];
    const float* w41 = (const float*)d_in[10];
    const float* b41 = (const float*)d_in[11];
    const float* w42 = (const float*)d_in[12];
    const float* b42 = (const float*)d_in[13];
    float* out = (float*)d_out;

    const size_t SM2 = (size_t)(S2_IN + S2_W + 2*C2)*sizeof(float);
    const size_t SM3 = (size_t)(S3_IN + S3_W + 32+32+64+128+8)*sizeof(float);
    const size_t SMF = (size_t)TOPK*32*sizeof(unsigned int);
    cudaFuncSetAttribute(k_conv2,      cudaFuncAttributeMaxDynamicSharedMemorySize, (int)SM2);
    cudaFuncSetAttribute(k_conv3fused, cudaFuncAttributeMaxDynamicSharedMemorySize, (int)SM3);
    cudaFuncSetAttribute(k_final,      cudaFuncAttributeMaxDynamicSharedMemorySize, (int)SMF);

    dim3 blk(32,8);
    k_conv1pool<<<dim3((PW+31)/32,(PH+7)/8,BATCH), blk>>>(x,w1,b1,a1);
    k_conv2<<<dim3((W2+63)/64,(H2+15)/16,BATCH), blk, SM2>>>(w2,b2,a2);
    k_conv3fused<<<dim3((W3+63)/64,(H3+7)/8,BATCH), blk, SM3>>>(w3,b3,a3,w41,b41,w42,b42);
    k_reset16<<<64,1024>>>();
    for (int p=0;p<4;p++){
        k_hist16<<<2048,256>>>(p);
        k_pick16<<<1,1024>>>();
    }
    k_compact<<<2048,256>>>();
    k_sort<<<1,TOPK>>>();
    k_mask<<<(TOPK*32)/256,256>>>();
    k_final<<<1,TOPK,SMF>>>(out);
}

// round 7
// speedup vs baseline: 1.0004x; 1.0004x over previous
#include <cuda_runtime.h>
#include <math.h>

#define BATCH 4
#define IN_H 1080
#define IN_W 1920
#define C1 10
#define PH 539
#define PW 959
#define C2 16
#define H2 537
#define W2 957
#define C3 32
#define H3 535
#define W3 955
#define NPIX (H3*W3)            // 510925
#define TOT (BATCH*NPIX)        // 2043700
#define TOPK 1024

// ---------------- scratch (static device memory; no allocations) ----------------
__device__ float g_pool[BATCH*C1*PH*PW];
__device__ float g_c2[BATCH*C2*H2*W2];
__device__ float g_pred[TOT*4];
__device__ __align__(16) unsigned long long g_keys[TOT];
__device__ unsigned int g_hist16[65536];
__device__ unsigned long long g_prefix;
__device__ int g_remaining;
__device__ unsigned long long g_top[TOPK];
__device__ int g_topcnt;
__device__ float4 g_boxo[TOPK];
__device__ int g_valid[TOPK];
__device__ unsigned int g_nmsmask[TOPK*32];

// ---------------- conv1 (3->10, 3x3) + PReLU + 2x2 maxpool ----------------
// Reduction order: ky -> kx -> ci (ci innermost), FMA chain, bias added at END.
__global__ __launch_bounds__(256,2) void k_conv1pool(
    const float* __restrict__ x, const float* __restrict__ w,
    const float* __restrict__ bias, const float* __restrict__ alpha)
{
    __shared__ __align__(16) float s_in[3*18*66];
    __shared__ __align__(16) float s_w[27*12];
    __shared__ float s_b[C1], s_a[C1];
    const int tx = threadIdx.x, ty = threadIdx.y;
    const int tid = ty*32 + tx;
    const int b = blockIdx.z;
    const int px0 = blockIdx.x*32, py0 = blockIdx.y*8;
    const int ix0 = px0*2, iy0 = py0*2;

    for (int i = tid; i < 270; i += 256) {
        int st = i/10, co = i%10;
        int ci = st % 3; int r = st / 3; int ky = r/3, kx = r%3;
        s_w[st*12+co] = w[co*27 + ci*9 + ky*3 + kx];
    }
    if (tid < C1) { s_b[tid]=bias[tid]; s_a[tid]=alpha[tid]; }
    for (int i = tid; i < 3*18*66; i += 256) {
        int c = i/(18*66); int r = (i/66)%18; int cc = i%66;
        int gy = iy0 + r, gx = ix0 + cc;
        float v = 0.f;
        if (gy < IN_H && gx < IN_W) v = x[((b*3 + c)*IN_H + gy)*IN_W + gx];
        s_in[i] = v;
    }
    __syncthreads();
    const int px = px0 + tx, py = py0 + ty;
    if (px >= PW || py >= PH) return;

    float acc[4][C1];
    #pragma unroll
    for (int p=0;p<4;p++)
      #pragma unroll
      for (int co=0;co<C1;co++) acc[p][co] = 0.f;

    #pragma unroll
    for (int ky=0;ky<3;ky++){
      #pragma unroll
      for (int kx=0;kx<3;kx++){
        #pragma unroll
        for (int ci=0;ci<3;ci++){
          const int st = (ky*3+kx)*3+ci;
          const float4 wa = *(const float4*)&s_w[st*12];
          const float4 wb = *(const float4*)&s_w[st*12+4];
          const float2 wc = *(const float2*)&s_w[st*12+8];
          const float wv[10] = {wa.x,wa.y,wa.z,wa.w, wb.x,wb.y,wb.z,wb.w, wc.x,wc.y};
          float v[4];
          #pragma unroll
          for (int pyi=0;pyi<2;pyi++)
            #pragma unroll
            for (int pxi=0;pxi<2;pxi++)
              v[pyi*2+pxi] = s_in[ci*(18*66) + (2*ty+pyi+ky)*66 + (2*tx+pxi+kx)];
          #pragma unroll
          for (int p=0;p<4;p++)
            #pragma unroll
            for (int co=0;co<C1;co++)
              acc[p][co] = __fmaf_rn(v[p], wv[co], acc[p][co]);
        }
      }
    }
    #pragma unroll
    for (int co=0;co<C1;co++){
      float m = -1e30f;
      #pragma unroll
      for (int p=0;p<4;p++){
        float t = acc[p][co] + s_b[co];
        t = (t >= 0.f) ? t : s_a[co]*t;
        m = fmaxf(m, t);
      }
      g_pool[((b*C1+co)*PH+py)*PW+px] = m;
    }
}

// ---------------- conv2 (10->16, 3x3) + PReLU ----------------
#define S2_IN (10*18*66)   // 11880
#define S2_W  (90*16)      // 1440
__global__ __launch_bounds__(256,2) void k_conv2(
    const float* __restrict__ w, const float* __restrict__ bias, const float* __restrict__ alpha)
{
    extern __shared__ float sm2[];
    float* s_in = sm2;
    float* s_w  = sm2 + S2_IN;
    float* s_b  = s_w + S2_W;
    float* s_a  = s_b + C2;
    const int tx = threadIdx.x, ty = threadIdx.y;
    const int tid = ty*32+tx;
    const int b = blockIdx.z;
    const int ox0 = blockIdx.x*64, oy0 = blockIdx.y*16;

    for (int i = tid; i < S2_W; i += 256){
        int st=i/16, co=i%16;
        int ci = st % 10; int r = st / 10; int ky = r/3, kx = r%3;
        s_w[i] = w[co*90 + ci*9 + ky*3 + kx];
    }
    if (tid < C2){ s_b[tid]=bias[tid]; s_a[tid]=alpha[tid]; }
    for (int i = tid; i < S2_IN; i += 256){
        int ci = i/(18*66); int r=(i/66)%18; int cc=i%66;
        int gy=oy0+r, gx=ox0+cc;
        float v=0.f;
        if (gy<PH && gx<PW) v = g_pool[((b*C1+ci)*PH+gy)*PW+gx];
        s_in[i]=v;
    }
    __syncthreads();

    float acc[4][C2];
    #pragma unroll
    for (int p=0;p<4;p++)
      #pragma unroll
      for (int co=0;co<C2;co++) acc[p][co]=0.f;

    #pragma unroll
    for (int ky=0;ky<3;ky++){
      #pragma unroll
      for (int kx=0;kx<3;kx++){
        #pragma unroll 1
        for (int ci=0;ci<C1;ci++){
          const int st = (ky*3+kx)*10+ci;
          const float4 w0 = *(const float4*)&s_w[st*16];
          const float4 w1 = *(const float4*)&s_w[st*16+4];
          const float4 w2 = *(const float4*)&s_w[st*16+8];
          const float4 w3 = *(const float4*)&s_w[st*16+12];
          const float wv[16] = {w0.x,w0.y,w0.z,w0.w, w1.x,w1.y,w1.z,w1.w,
                                w2.x,w2.y,w2.z,w2.w, w3.x,w3.y,w3.z,w3.w};
          float v[4];
          #pragma unroll
          for (int pyi=0;pyi<2;pyi++)
            #pragma unroll
            for (int pxi=0;pxi<2;pxi++)
              v[pyi*2+pxi] = s_in[ci*(18*66) + (ty+8*pyi+ky)*66 + (tx+32*pxi+kx)];
          #pragma unroll
          for (int p=0;p<4;p++)
            #pragma unroll
            for (int co=0;co<C2;co++)
              acc[p][co] = __fmaf_rn(v[p], wv[co], acc[p][co]);
        }
      }
    }
    #pragma unroll
    for (int pyi=0;pyi<2;pyi++){
      int oy = oy0 + ty + 8*pyi;
      #pragma unroll
      for (int pxi=0;pxi<2;pxi++){
        int ox = ox0 + tx + 32*pxi;
        if (oy < H2 && ox < W2){
          int p = pyi*2+pxi;
          #pragma unroll
          for (int co=0;co<C2;co++){
            float t = acc[p][co] + s_b[co];
            t = (t>=0.f) ? t : s_a[co]*t;
            g_c2[((b*C2+co)*H2+oy)*W2+ox] = t;
          }
        }
      }
    }
}

// ------- conv3 (16->32, 3x3) + PReLU + 1x1 heads + softmax + key emit -------
#define S3_IN (16*10*66)   // 10560
#define S3_W  (144*32)     // 4608
__global__ __launch_bounds__(256,1) void k_conv3fused(
    const float* __restrict__ w3, const float* __restrict__ b3, const float* __restrict__ a3,
    const float* __restrict__ w41, const float* __restrict__ b41,
    const float* __restrict__ w42, const float* __restrict__ b42)
{
    extern __shared__ float sm3[];
    float* s_in  = sm3;
    float* s_w   = sm3 + S3_IN;
    float* s_b   = s_w + S3_W;     // 32
    float* s_a   = s_b + 32;       // 32
    float* s_w41 = s_a + 32;       // 64
    float* s_w42 = s_w41 + 64;     // 128
    float* s_b4  = s_w42 + 128;    // 8
    const int tx=threadIdx.x, ty=threadIdx.y, tid=ty*32+tx;
    const int b = blockIdx.z;
    const int ox0 = blockIdx.x*64, oy0 = blockIdx.y*8;

    for (int i=tid;i<S3_W;i+=256){
        int st=i/32, co=i%32;
        int ci = st % 16; int r = st / 16; int ky = r/3, kx = r%3;
        s_w[i] = w3[co*144 + ci*9 + ky*3 + kx];
    }
    if (tid<32){ s_b[tid]=b3[tid]; s_a[tid]=a3[tid]; }
    if (tid<64)  s_w41[tid]=w41[tid];
    if (tid<128) s_w42[tid]=w42[tid];
    if (tid<2)   s_b4[tid]=b41[tid];
    if (tid>=4 && tid<8) s_b4[tid-2]=b42[tid-4];
    for (int i=tid;i<S3_IN;i+=256){
        int ci=i/(10*66); int r=(i/66)%10; int cc=i%66;
        int gy=oy0+r, gx=ox0+cc;
        float v=0.f;
        if (gy<H2 && gx<W2) v = g_c2[((b*C2+ci)*H2+gy)*W2+gx];
        s_in[i]=v;
    }
    __syncthreads();

    float acc[2][C3];
    #pragma unroll
    for (int co=0;co<C3;co++){ acc[0][co]=0.f; acc[1][co]=0.f; }

    #pragma unroll
    for (int ky=0;ky<3;ky++){
      #pragma unroll
      for (int kx=0;kx<3;kx++){
        #pragma unroll 1
        for (int ci=0;ci<16;ci++){
          const int st = (ky*3+kx)*16+ci;
          float wv[32];
          #pragma unroll
          for (int q=0;q<8;q++){
            float4 t4 = *(const float4*)&s_w[st*32 + q*4];
            wv[q*4]=t4.x; wv[q*4+1]=t4.y; wv[q*4+2]=t4.z; wv[q*4+3]=t4.w;
          }
          const float v0 = s_in[ci*660 + (ty+ky)*66 + (tx+kx)];
          const float v1 = s_in[ci*660 + (ty+ky)*66 + (tx+32+kx)];
          #pragma unroll
          for (int co=0;co<32;co++){
            acc[0][co] = __fmaf_rn(v0, wv[co], acc[0][co]);
            acc[1][co] = __fmaf_rn(v1, wv[co], acc[1][co]);
          }
        }
      }
    }

    const int oy = oy0 + ty;
    #pragma unroll
    for (int p=0;p<2;p++){
      const int ox = ox0 + tx + 32*p;
      if (oy < H3 && ox < W3){
        float l0 = 0.f, l1 = 0.f;
        float pr0=0.f, pr1=0.f, pr2=0.f, pr3=0.f;
        #pragma unroll
        for (int co=0;co<32;co++){
          float h = acc[p][co] + s_b[co];
          h = (h>=0.f) ? h : s_a[co]*h;
          l0  = __fmaf_rn(h, s_w41[co],     l0);
          l1  = __fmaf_rn(h, s_w41[32+co],  l1);
          pr0 = __fmaf_rn(h, s_w42[co],     pr0);
          pr1 = __fmaf_rn(h, s_w42[32+co],  pr1);
          pr2 = __fmaf_rn(h, s_w42[64+co],  pr2);
          pr3 = __fmaf_rn(h, s_w42[96+co],  pr3);
        }
        l0 += s_b4[0]; l1 += s_b4[1];
        pr0 += s_b4[2]; pr1 += s_b4[3]; pr2 += s_b4[4]; pr3 += s_b4[5];
        float m  = fmaxf(l0,l1);
        float e0 = expf(l0-m), e1 = expf(l1-m);
        float score = __fdiv_rn(e1, __fadd_rn(e0,e1));
        int gidx = b*NPIX + oy*W3 + ox;
        unsigned long long key;
        if (score >= 0.6f){
          unsigned u = __float_as_uint(score) | 0x80000000u;
          key = ((unsigned long long)u << 32) | (unsigned long long)(0xFFFFFFFFu - (unsigned)gidx);
        } else {
          key = (unsigned long long)(unsigned)gidx;
        }
        g_keys[gidx] = key;
        g_pred[gidx*4+0]=pr0; g_pred[gidx*4+1]=pr1; g_pred[gidx*4+2]=pr2; g_pred[gidx*4+3]=pr3;
      }
    }
}

// ---------------- exact top-K: 4-pass 16-bit MSB radix select ----------------
__global__ void k_reset16(){
    g_hist16[blockIdx.x*1024+threadIdx.x]=0u;
    if (blockIdx.x==0 && threadIdx.x==0){ g_prefix=0ULL; g_remaining=TOPK; g_topcnt=0; }
}

__global__ void k_hist16(int p){
    int t = blockIdx.x*blockDim.x + threadIdx.x;
    int stride = gridDim.x*blockDim.x;
    unsigned long long pref = g_prefix;
    int shd = 48 - 16*p;
    const ulonglong2* keys2 = (const ulonglong2*)g_keys;
    for (int i = t; i < TOT/2; i += stride){
        ulonglong2 kk = keys2[i];
        bool ok0 = (p==0) || ((kk.x >> (64-16*p)) == pref);
        bool ok1 = (p==0) || ((kk.y >> (64-16*p)) == pref);
        if (ok0) atomicAdd(&g_hist16[(unsigned)(kk.x>>shd)&0xFFFFu], 1u);
        if (ok1) atomicAdd(&g_hist16[(unsigned)(kk.y>>shd)&0xFFFFu], 1u);
    }
}

__global__ void k_pick16(){   // <<<1,1024>>>
    __shared__ unsigned int ssum[1024];
    int t = threadIdx.x;
    unsigned base = (unsigned)t*64u;
    unsigned s = 0;
    #pragma unroll 8
    for (int i=0;i<64;i++) s += g_hist16[base+i];
    ssum[t] = s;
    __syncthreads();
    // inclusive suffix scan (Hillis-Steele)
    for (int off=1; off<1024; off<<=1){
        unsigned v = (t+off<1024) ? ssum[t+off] : 0u;
        __syncthreads();
        ssum[t] += v;
        __syncthreads();
    }
    unsigned r = (unsigned)g_remaining;
    unsigned above = (t<1023) ? ssum[t+1] : 0u;
    if (above < r && above + s >= r){
        unsigned c = above;
        for (int i=63;i>=0;i--){
            unsigned h = g_hist16[base+i];
            if (c + h >= r){
                g_prefix = (g_prefix<<16) | (unsigned long long)(base+(unsigned)i);
                g_remaining = (int)(r - c);
                break;
            }
            c += h;
        }
    }
    #pragma unroll 8
    for (int i=0;i<64;i++) g_hist16[base+i]=0u;
}

__global__ void k_compact(){
    unsigned long long T = g_prefix;   // exact 1024th-largest key
    int t = blockIdx.x*blockDim.x + threadIdx.x;
    int stride = gridDim.x*blockDim.x;
    const ulonglong2* keys2 = (const ulonglong2*)g_keys;
    for (int i = t; i < TOT/2; i += stride){
        ulonglong2 kk = keys2[i];
        if (kk.x >= T){
            int pos = atomicAdd(&g_topcnt, 1);
            if (pos < TOPK) g_top[pos] = kk.x;
        }
        if (kk.y >= T){
            int pos = atomicAdd(&g_topcnt, 1);
            if (pos < TOPK) g_top[pos] = kk.y;
        }
    }
}

// ---------------- bitonic sort (desc) + box decode ----------------
__global__ void k_sort(){
    __shared__ unsigned long long sk[TOPK];
    int t = threadIdx.x;
    sk[t] = g_top[t];
    for (int size=2; size<=TOPK; size<<=1){
      for (int stride=size>>1; stride>0; stride>>=1){
        __syncthreads();
        int j = t ^ stride;
        if (j > t){
          unsigned long long a = sk[t], c = sk[j];
          bool desc = ((t & size) == 0);
          bool sw = desc ? (a < c) : (a > c);
          if (sw){ sk[t]=c; sk[j]=a; }
        }
      }
    }
    __syncthreads();
    unsigned long long key = sk[t];
    g_top[t] = key;
    int valid = (key >> 32) != 0ULL;
    int idx = valid ? (int)(0xFFFFFFFFu - (unsigned)(key & 0xFFFFFFFFULL)) : 0;
    int bb = idx / NPIX; int rem = idx - bb*NPIX;
    int oy = rem / W3;   int ox = rem - oy*W3;
    float off = valid ? 100000.f * (float)bb : 0.f;
    float4 box;
    box.x = (float)(2*ox+1)  + off;
    box.y = (float)(2*oy+1)  + off;
    box.z = (float)(2*ox+12) + off;
    box.w = (float)(2*oy+12) + off;
    g_boxo[t]  = box;
    g_valid[t] = valid;
}

// ---------------- pairwise suppression bits ----------------
__global__ void k_mask(){
    int tid = blockIdx.x*blockDim.x + threadIdx.x;
    int i = tid >> 5;
    int w = tid & 31;
    if (i >= TOPK) return;
    float4 bi = g_boxo[i];
    float ai = (bi.z-bi.x)*(bi.w-bi.y);
    unsigned m = 0u;
    #pragma unroll 4
    for (int t2=0;t2<32;t2++){
        int j = w*32 + t2;
        float4 bj = g_boxo[j];
        float aj = (bj.z-bj.x)*(bj.w-bj.y);
        float xx1=fmaxf(bi.x,bj.x), yy1=fmaxf(bi.y,bj.y);
        float xx2=fminf(bi.z,bj.z), yy2=fminf(bi.w,bj.w);
        float inter = fmaxf(xx2-xx1,0.f)*fmaxf(yy2-yy1,0.f);
        float iou = __fdiv_rn(inter, ai+aj-inter);
        if (j > i && iou > 0.5f) m |= (1u<<t2);
    }
    g_nmsmask[i*32+w] = m;
}

// ---------------- sequential greedy NMS + refine + output ----------------
__global__ void k_final(float* __restrict__ out){
    extern __shared__ unsigned int smm[];     // TOPK*32 words
    __shared__ unsigned int s_keepw[32];
    int t = threadIdx.x;
    for (int i=t; i<TOPK*32; i+=TOPK) smm[i] = g_nmsmask[i];
    __syncthreads();
    if (t < 32){
        unsigned vword = 0u;
        for (int q=0;q<32;q++) vword |= (g_valid[t*32+q] ? 1u:0u) << q;
        unsigned sup = 0u, keepw = 0u;
        for (int i=0;i<TOPK;i++){
            int l = i >> 5, bb = i & 31;
            unsigned sw = __shfl_sync(0xffffffffu, sup,   l);
            unsigned vw = __shfl_sync(0xffffffffu, vword, l);
            bool keep = !((sw >> bb) & 1u) && ((vw >> bb) & 1u);
            if (keep) sup |= smm[i*32 + t];
            if (t == l) keepw |= ((unsigned)keep) << bb;
        }
        s_keepw[t] = keepw;
    }
    __syncthreads();
    bool keep = (s_keepw[t>>5] >> (t&31)) & 1u;
    float o0=0.f,o1=0.f,o2=0.f,o3=0.f,o4=0.f;
    if (keep){
        unsigned long long key = g_top[t];
        unsigned u = (unsigned)(key>>32);
        float score = __uint_as_float(u & 0x7FFFFFFFu);
        int idx = (int)(0xFFFFFFFFu - (unsigned)(key & 0xFFFFFFFFULL));
        int rem = idx % NPIX;
        int oy = rem / W3; int ox = rem - oy*W3;
        float x1 = (float)(2*ox+1),  y1 = (float)(2*oy+1);
        float x2 = (float)(2*ox+12), y2 = (float)(2*oy+12);
        float bw = x2-x1, bh = y2-y1;
        float p0 = g_pred[idx*4+0], p1=g_pred[idx*4+1], p2=g_pred[idx*4+2], p3=g_pred[idx*4+3];
        float r0 = x1 + p0*bw;
        float r1 = y1 + p1*bh;
        float r2 = x2 + p2*bw;
        float r3 = y2 + p3*bh;
        float rw = r2-r0, rh = r3-r1;
        float L = fmaxf(rw, rh);
        float nx1 = r0 + 0.5f*rw - 0.5f*L;
        float ny1 = r1 + 0.5f*rh - 0.5f*L;
        o0=nx1; o1=ny1; o2=nx1+L; o3=ny1+L; o4=score;
    }
    out[t*5+0]=o0; out[t*5+1]=o1; out[t*5+2]=o2; out[t*5+3]=o3; out[t*5+4]=o4;
}

// ---------------- launch ----------------
extern "C" void kernel_launch(void* const* d_in, const int* in_sizes, int n_in,
                              void* d_out, int out_size){
    const float* x   = (const float*)d_in[0];
    const float* w1  = (const float*)d_in[1];
    const float* b1  = (const float*)d_in[2];
    const float* a1  = (const float*)d_in[3];
    const float* w2  = (const float*)d_in[4];
    const float* b2  = (const float*)d_in[5];
    const float* a2  = (const float*)d_in[6];
    const float* w3  = (const float*)d_in[7];
    const float* b3  = (const float*)d_in[8];
    const float* a3  = (const float*)d_in[9];
    const float* w41 = (const float*)d_in[10];
    const float* b41 = (const float*)d_in[11];
    const float* w42 = (const float*)d_in[12];
    const float* b42 = (const float*)d_in[13];
    float* out = (float*)d_out;

    const size_t SM2 = (size_t)(S2_IN + S2_W + 2*C2)*sizeof(float);
    const size_t SM3 = (size_t)(S3_IN + S3_W + 32+32+64+128+8)*sizeof(float);
    const size_t SMF = (size_t)TOPK*32*sizeof(unsigned int);
    cudaFuncSetAttribute(k_conv2,      cudaFuncAttributeMaxDynamicSharedMemorySize, (int)SM2);
    cudaFuncSetAttribute(k_conv3fused, cudaFuncAttributeMaxDynamicSharedMemorySize, (int)SM3);
    cudaFuncSetAttribute(k_final,      cudaFuncAttributeMaxDynamicSharedMemorySize, (int)SMF);

    dim3 blk(32,8);
    k_conv1pool<<<dim3((PW+31)/32,(PH+7)/8,BATCH), blk>>>(x,w1,b1,a1);
    k_conv2<<<dim3((W2+63)/64,(H2+15)/16,BATCH), blk, SM2>>>(w2,b2,a2);
    k_conv3fused<<<dim3((W3+63)/64,(H3+7)/8,BATCH), blk, SM3>>>(w3,b3,a3,w41,b41,w42,b42);
    k_reset16<<<64,1024>>>();
    for (int p=0;p<4;p++){
        k_hist16<<<2048,256>>>(p);
        k_pick16<<<1,1024>>>();
    }
    k_compact<<<2048,256>>>();
    k_sort<<<1,TOPK>>>();
    k_mask<<<(TOPK*32)/256,256>>>();
    k_final<<<1,TOPK,SMF>>>(out);
}

// round 8
// speedup vs baseline: 1.9781x; 1.9772x over previous
#include <cuda_runtime.h>
#include <math.h>

#define BATCH 4
#define IN_H 1080
#define IN_W 1920
#define C1 10
#define PH 539
#define PW 959
#define C2 16
#define H2 537
#define W2 957
#define C3 32
#define H3 535
#define W3 955
#define NPIX (H3*W3)            // 510925
#define TOT (BATCH*NPIX)        // 2043700
#define TOPK 1024

// ---------------- scratch (static device memory; no allocations) ----------------
__device__ float g_pool[BATCH*C1*PH*PW];
__device__ float g_c2[BATCH*C2*H2*W2];
__device__ float g_pred[TOT*4];
__device__ unsigned long long g_keys[TOT];
__device__ unsigned int g_hist[256];
__device__ unsigned long long g_prefix;
__device__ int g_remaining;
__device__ unsigned long long g_top[TOPK];
__device__ int g_topcnt;
__device__ float4 g_boxo[TOPK];
__device__ int g_valid[TOPK];
__device__ unsigned int g_nmsmask[TOPK*32];

// ---------------- conv1 (3->10, 3x3) + PReLU + 2x2 maxpool ----------------
// Reduction order: ky -> kx -> ci (ci innermost), FMA chain, bias added at END.
__global__ __launch_bounds__(256,2) void k_conv1pool(
    const float* __restrict__ x, const float* __restrict__ w,
    const float* __restrict__ bias, const float* __restrict__ alpha)
{
    __shared__ __align__(16) float s_in[3*18*66];
    __shared__ __align__(16) float s_w[27*12];
    __shared__ float s_b[C1], s_a[C1];
    const int tx = threadIdx.x, ty = threadIdx.y;
    const int tid = ty*32 + tx;
    const int b = blockIdx.z;
    const int px0 = blockIdx.x*32, py0 = blockIdx.y*8;
    const int ix0 = px0*2, iy0 = py0*2;

    for (int i = tid; i < 270; i += 256) {
        int st = i/10, co = i%10;
        int ci = st % 3; int r = st / 3; int ky = r/3, kx = r%3;
        s_w[st*12+co] = w[co*27 + ci*9 + ky*3 + kx];
    }
    if (tid < C1) { s_b[tid]=bias[tid]; s_a[tid]=alpha[tid]; }
    for (int i = tid; i < 3*18*66; i += 256) {
        int c = i/(18*66); int r = (i/66)%18; int cc = i%66;
        int gy = iy0 + r, gx = ix0 + cc;
        float v = 0.f;
        if (gy < IN_H && gx < IN_W) v = x[((b*3 + c)*IN_H + gy)*IN_W + gx];
        s_in[i] = v;
    }
    __syncthreads();
    const int px = px0 + tx, py = py0 + ty;
    if (px >= PW || py >= PH) return;

    float acc[4][C1];
    #pragma unroll
    for (int p=0;p<4;p++)
      #pragma unroll
      for (int co=0;co<C1;co++) acc[p][co] = 0.f;

    #pragma unroll
    for (int ky=0;ky<3;ky++){
      #pragma unroll
      for (int kx=0;kx<3;kx++){
        #pragma unroll
        for (int ci=0;ci<3;ci++){
          const int st = (ky*3+kx)*3+ci;
          const float4 wa = *(const float4*)&s_w[st*12];
          const float4 wb = *(const float4*)&s_w[st*12+4];
          const float2 wc = *(const float2*)&s_w[st*12+8];
          const float wv[10] = {wa.x,wa.y,wa.z,wa.w, wb.x,wb.y,wb.z,wb.w, wc.x,wc.y};
          float v[4];
          #pragma unroll
          for (int pyi=0;pyi<2;pyi++)
            #pragma unroll
            for (int pxi=0;pxi<2;pxi++)
              v[pyi*2+pxi] = s_in[ci*(18*66) + (2*ty+pyi+ky)*66 + (2*tx+pxi+kx)];
          #pragma unroll
          for (int p=0;p<4;p++)
            #pragma unroll
            for (int co=0;co<C1;co++)
              acc[p][co] = __fmaf_rn(v[p], wv[co], acc[p][co]);
        }
      }
    }
    #pragma unroll
    for (int co=0;co<C1;co++){
      float m = -1e30f;
      #pragma unroll
      for (int p=0;p<4;p++){
        float t = acc[p][co] + s_b[co];
        t = (t >= 0.f) ? t : s_a[co]*t;
        m = fmaxf(m, t);
      }
      g_pool[((b*C1+co)*PH+py)*PW+px] = m;
    }
}

// ---------------- conv2 (10->16, 3x3) + PReLU ----------------
#define S2_IN (10*18*66)   // 11880
#define S2_W  (90*16)      // 1440
__global__ __launch_bounds__(256,2) void k_conv2(
    const float* __restrict__ w, const float* __restrict__ bias, const float* __restrict__ alpha)
{
    extern __shared__ float sm2[];
    float* s_in = sm2;
    float* s_w  = sm2 + S2_IN;
    float* s_b  = s_w + S2_W;
    float* s_a  = s_b + C2;
    const int tx = threadIdx.x, ty = threadIdx.y;
    const int tid = ty*32+tx;
    const int b = blockIdx.z;
    const int ox0 = blockIdx.x*64, oy0 = blockIdx.y*16;

    for (int i = tid; i < S2_W; i += 256){
        int st=i/16, co=i%16;
        int ci = st % 10; int r = st / 10; int ky = r/3, kx = r%3;
        s_w[i] = w[co*90 + ci*9 + ky*3 + kx];
    }
    if (tid < C2){ s_b[tid]=bias[tid]; s_a[tid]=alpha[tid]; }
    for (int i = tid; i < S2_IN; i += 256){
        int ci = i/(18*66); int r=(i/66)%18; int cc=i%66;
        int gy=oy0+r, gx=ox0+cc;
        float v=0.f;
        if (gy<PH && gx<PW) v = g_pool[((b*C1+ci)*PH+gy)*PW+gx];
        s_in[i]=v;
    }
    __syncthreads();

    float acc[4][C2];
    #pragma unroll
    for (int p=0;p<4;p++)
      #pragma unroll
      for (int co=0;co<C2;co++) acc[p][co]=0.f;

    #pragma unroll
    for (int ky=0;ky<3;ky++){
      #pragma unroll
      for (int kx=0;kx<3;kx++){
        #pragma unroll 1
        for (int ci=0;ci<C1;ci++){
          const int st = (ky*3+kx)*10+ci;
          const float4 w0 = *(const float4*)&s_w[st*16];
          const float4 w1 = *(const float4*)&s_w[st*16+4];
          const float4 w2 = *(const float4*)&s_w[st*16+8];
          const float4 w3 = *(const float4*)&s_w[st*16+12];
          const float wv[16] = {w0.x,w0.y,w0.z,w0.w, w1.x,w1.y,w1.z,w1.w,
                                w2.x,w2.y,w2.z,w2.w, w3.x,w3.y,w3.z,w3.w};
          float v[4];
          #pragma unroll
          for (int pyi=0;pyi<2;pyi++)
            #pragma unroll
            for (int pxi=0;pxi<2;pxi++)
              v[pyi*2+pxi] = s_in[ci*(18*66) + (ty+8*pyi+ky)*66 + (tx+32*pxi+kx)];
          #pragma unroll
          for (int p=0;p<4;p++)
            #pragma unroll
            for (int co=0;co<C2;co++)
              acc[p][co] = __fmaf_rn(v[p], wv[co], acc[p][co]);
        }
      }
    }
    #pragma unroll
    for (int pyi=0;pyi<2;pyi++){
      int oy = oy0 + ty + 8*pyi;
      #pragma unroll
      for (int pxi=0;pxi<2;pxi++){
        int ox = ox0 + tx + 32*pxi;
        if (oy < H2 && ox < W2){
          int p = pyi*2+pxi;
          #pragma unroll
          for (int co=0;co<C2;co++){
            float t = acc[p][co] + s_b[co];
            t = (t>=0.f) ? t : s_a[co]*t;
            g_c2[((b*C2+co)*H2+oy)*W2+ox] = t;
          }
        }
      }
    }
}

// ------- conv3 (16->32, 3x3) + PReLU + 1x1 heads + softmax + key emit -------
// 4 pixels per thread (128-wide tile) to amortize weight LDS over 2x the FMAs.
#define S3_IN (16*10*130)  // 20800
#define S3_W  (144*32)     // 4608
__global__ __launch_bounds__(256,1) void k_conv3fused(
    const float* __restrict__ w3, const float* __restrict__ b3, const float* __restrict__ a3,
    const float* __restrict__ w41, const float* __restrict__ b41,
    const float* __restrict__ w42, const float* __restrict__ b42)
{
    extern __shared__ float sm3[];
    float* s_in  = sm3;
    float* s_w   = sm3 + S3_IN;
    float* s_b   = s_w + S3_W;     // 32
    float* s_a   = s_b + 32;       // 32
    float* s_w41 = s_a + 32;       // 64
    float* s_w42 = s_w41 + 64;     // 128
    float* s_b4  = s_w42 + 128;    // 8
    const int tx=threadIdx.x, ty=threadIdx.y, tid=ty*32+tx;
    const int b = blockIdx.z;
    const int ox0 = blockIdx.x*128, oy0 = blockIdx.y*8;

    for (int i=tid;i<S3_W;i+=256){
        int st=i/32, co=i%32;
        int ci = st % 16; int r = st / 16; int ky = r/3, kx = r%3;
        s_w[i] = w3[co*144 + ci*9 + ky*3 + kx];
    }
    if (tid<32){ s_b[tid]=b3[tid]; s_a[tid]=a3[tid]; }
    if (tid<64)  s_w41[tid]=w41[tid];
    if (tid<128) s_w42[tid]=w42[tid];
    if (tid<2)   s_b4[tid]=b41[tid];
    if (tid>=4 && tid<8) s_b4[tid-2]=b42[tid-4];
    for (int i=tid;i<S3_IN;i+=256){
        int ci=i/(10*130); int r=(i/130)%10; int cc=i%130;
        int gy=oy0+r, gx=ox0+cc;
        float v=0.f;
        if (gy<H2 && gx<W2) v = g_c2[((b*C2+ci)*H2+gy)*W2+gx];
        s_in[i]=v;
    }
    __syncthreads();

    float acc[4][C3];
    #pragma unroll
    for (int p=0;p<4;p++)
      #pragma unroll
      for (int co=0;co<C3;co++) acc[p][co]=0.f;

    #pragma unroll
    for (int ky=0;ky<3;ky++){
      #pragma unroll
      for (int kx=0;kx<3;kx++){
        #pragma unroll 1
        for (int ci=0;ci<16;ci++){
          const int st = (ky*3+kx)*16+ci;
          float wv[32];
          #pragma unroll
          for (int q=0;q<8;q++){
            float4 t4 = *(const float4*)&s_w[st*32 + q*4];
            wv[q*4]=t4.x; wv[q*4+1]=t4.y; wv[q*4+2]=t4.z; wv[q*4+3]=t4.w;
          }
          const int base = ci*1300 + (ty+ky)*130 + tx + kx;
          float v[4];
          #pragma unroll
          for (int p=0;p<4;p++) v[p] = s_in[base + 32*p];
          #pragma unroll
          for (int co=0;co<32;co++){
            #pragma unroll
            for (int p=0;p<4;p++)
              acc[p][co] = __fmaf_rn(v[p], wv[co], acc[p][co]);
          }
        }
      }
    }

    const int oy = oy0 + ty;
    #pragma unroll
    for (int p=0;p<4;p++){
      const int ox = ox0 + tx + 32*p;
      if (oy < H3 && ox < W3){
        float l0 = 0.f, l1 = 0.f;
        float pr0=0.f, pr1=0.f, pr2=0.f, pr3=0.f;
        #pragma unroll
        for (int co=0;co<32;co++){
          float h = acc[p][co] + s_b[co];
          h = (h>=0.f) ? h : s_a[co]*h;
          l0  = __fmaf_rn(h, s_w41[co],     l0);
          l1  = __fmaf_rn(h, s_w41[32+co],  l1);
          pr0 = __fmaf_rn(h, s_w42[co],     pr0);
          pr1 = __fmaf_rn(h, s_w42[32+co],  pr1);
          pr2 = __fmaf_rn(h, s_w42[64+co],  pr2);
          pr3 = __fmaf_rn(h, s_w42[96+co],  pr3);
        }
        l0 += s_b4[0]; l1 += s_b4[1];
        pr0 += s_b4[2]; pr1 += s_b4[3]; pr2 += s_b4[4]; pr3 += s_b4[5];
        float m  = fmaxf(l0,l1);
        float e0 = expf(l0-m), e1 = expf(l1-m);
        float score = __fdiv_rn(e1, __fadd_rn(e0,e1));
        int gidx = b*NPIX + oy*W3 + ox;
        unsigned long long key;
        if (score >= 0.6f){
          unsigned u = __float_as_uint(score) | 0x80000000u;
          key = ((unsigned long long)u << 32) | (unsigned long long)(0xFFFFFFFFu - (unsigned)gidx);
        } else {
          key = (unsigned long long)(unsigned)gidx;
        }
        g_keys[gidx] = key;
        g_pred[gidx*4+0]=pr0; g_pred[gidx*4+1]=pr1; g_pred[gidx*4+2]=pr2; g_pred[gidx*4+3]=pr3;
      }
    }
}

// ---------------- exact top-K: 8-pass MSB radix select (smem-aggregated) ----------------
__global__ void k_reset(){
    int t = threadIdx.x;
    if (t < 256) g_hist[t]=0u;
    if (t == 0){ g_prefix=0ULL; g_remaining=TOPK; g_topcnt=0; }
}

__global__ void k_hist(int p){
    __shared__ unsigned int sh[256];
    int t = threadIdx.x;
    sh[t]=0u; __syncthreads();
    unsigned long long pref = g_prefix;
    int shd = 56 - 8*p;
    for (int i = blockIdx.x*blockDim.x + t; i < TOT; i += gridDim.x*blockDim.x){
        unsigned long long key = g_keys[i];
        bool ok = (p==0) || ((key >> (64-8*p)) == pref);
        if (ok) atomicAdd(&sh[(unsigned)(key>>shd)&255u], 1u);
    }
    __syncthreads();
    if (sh[t]) atomicAdd(&g_hist[t], sh[t]);
}

__global__ void k_pick(){
    __shared__ unsigned int sh[256];
    int t = threadIdx.x;
    sh[t] = g_hist[t];
    __syncthreads();
    if (t == 0){
        int r = g_remaining;
        unsigned c = 0;
        for (int d=255; d>=0; d--){
            unsigned h = sh[d];
            if (c + h >= (unsigned)r){
                g_prefix = (g_prefix<<8) | (unsigned long long)d;
                g_remaining = r - (int)c;
                break;
            }
            c += h;
        }
    }
    g_hist[t] = 0u;
}

__global__ void k_compact(){
    unsigned long long T = g_prefix;   // exact 1024th-largest key
    for (int i = blockIdx.x*blockDim.x + threadIdx.x; i < TOT; i += gridDim.x*blockDim.x){
        unsigned long long key = g_keys[i];
        if (key >= T){
            int pos = atomicAdd(&g_topcnt, 1);
            if (pos < TOPK) g_top[pos] = key;
        }
    }
}

// ---------------- bitonic sort (desc) + box decode ----------------
__global__ void k_sort(){
    __shared__ unsigned long long sk[TOPK];
    int t = threadIdx.x;
    sk[t] = g_top[t];
    for (int size=2; size<=TOPK; size<<=1){
      for (int stride=size>>1; stride>0; stride>>=1){
        __syncthreads();
        int j = t ^ stride;
        if (j > t){
          unsigned long long a = sk[t], c = sk[j];
          bool desc = ((t & size) == 0);
          bool sw = desc ? (a < c) : (a > c);
          if (sw){ sk[t]=c; sk[j]=a; }
        }
      }
    }
    __syncthreads();
    unsigned long long key = sk[t];
    g_top[t] = key;
    int valid = (key >> 32) != 0ULL;
    int idx = valid ? (int)(0xFFFFFFFFu - (unsigned)(key & 0xFFFFFFFFULL)) : 0;
    int bb = idx / NPIX; int rem = idx - bb*NPIX;
    int oy = rem / W3;   int ox = rem - oy*W3;
    float off = valid ? 100000.f * (float)bb : 0.f;
    float4 box;
    box.x = (float)(2*ox+1)  + off;
    box.y = (float)(2*oy+1)  + off;
    box.z = (float)(2*ox+12) + off;
    box.w = (float)(2*oy+12) + off;
    g_boxo[t]  = box;
    g_valid[t] = valid;
}

// ---------------- pairwise suppression bits ----------------
__global__ void k_mask(){
    int tid = blockIdx.x*blockDim.x + threadIdx.x;
    int i = tid >> 5;
    int w = tid & 31;
    if (i >= TOPK) return;
    float4 bi = g_boxo[i];
    float ai = (bi.z-bi.x)*(bi.w-bi.y);
    unsigned m = 0u;
    #pragma unroll 4
    for (int t2=0;t2<32;t2++){
        int j = w*32 + t2;
        float4 bj = g_boxo[j];
        float aj = (bj.z-bj.x)*(bj.w-bj.y);
        float xx1=fmaxf(bi.x,bj.x), yy1=fmaxf(bi.y,bj.y);
        float xx2=fminf(bi.z,bj.z), yy2=fminf(bi.w,bj.w);
        float inter = fmaxf(xx2-xx1,0.f)*fmaxf(yy2-yy1,0.f);
        float iou = __fdiv_rn(inter, ai+aj-inter);
        if (j > i && iou > 0.5f) m |= (1u<<t2);
    }
    g_nmsmask[i*32+w] = m;
}

// ---------------- sequential greedy NMS + refine + output ----------------
__global__ void k_final(float* __restrict__ out){
    extern __shared__ unsigned int smm[];     // TOPK*32 words
    __shared__ unsigned int s_keepw[32];
    int t = threadIdx.x;
    for (int i=t; i<TOPK*32; i+=TOPK) smm[i] = g_nmsmask[i];
    __syncthreads();
    if (t < 32){
        unsigned vword = 0u;
        for (int q=0;q<32;q++) vword |= (g_valid[t*32+q] ? 1u:0u) << q;
        unsigned sup = 0u, keepw = 0u;
        for (int i=0;i<TOPK;i++){
            int l = i >> 5, bb = i & 31;
            unsigned sw = __shfl_sync(0xffffffffu, sup,   l);
            unsigned vw = __shfl_sync(0xffffffffu, vword, l);
            bool keep = !((sw >> bb) & 1u) && ((vw >> bb) & 1u);
            if (keep) sup |= smm[i*32 + t];
            if (t == l) keepw |= ((unsigned)keep) << bb;
        }
        s_keepw[t] = keepw;
    }
    __syncthreads();
    bool keep = (s_keepw[t>>5] >> (t&31)) & 1u;
    float o0=0.f,o1=0.f,o2=0.f,o3=0.f,o4=0.f;
    if (keep){
        unsigned long long key = g_top[t];
        unsigned u = (unsigned)(key>>32);
        float score = __uint_as_float(u & 0x7FFFFFFFu);
        int idx = (int)(0xFFFFFFFFu - (unsigned)(key & 0xFFFFFFFFULL));
        int rem = idx % NPIX;
        int oy = rem / W3; int ox = rem - oy*W3;
        float x1 = (float)(2*ox+1),  y1 = (float)(2*oy+1);
        float x2 = (float)(2*ox+12), y2 = (float)(2*oy+12);
        float bw = x2-x1, bh = y2-y1;
        float p0 = g_pred[idx*4+0], p1=g_pred[idx*4+1], p2=g_pred[idx*4+2], p3=g_pred[idx*4+3];
        float r0 = x1 + p0*bw;
        float r1 = y1 + p1*bh;
        float r2 = x2 + p2*bw;
        float r3 = y2 + p3*bh;
        float rw = r2-r0, rh = r3-r1;
        float L = fmaxf(rw, rh);
        float nx1 = r0 + 0.5f*rw - 0.5f*L;
        float ny1 = r1 + 0.5f*rh - 0.5f*L;
        o0=nx1; o1=ny1; o2=nx1+L; o3=ny1+L; o4=score;
    }
    out[t*5+0]=o0; out[t*5+1]=o1; out[t*5+2]=o2; out[t*5+3]=o3; out[t*5+4]=o4;
}

// ---------------- launch ----------------
extern "C" void kernel_launch(void* const* d_in, const int* in_sizes, int n_in,
                              void* d_out, int out_size){
    const float* x   = (const float*)d_in[0];
    const float* w1  = (const float*)d_in[1];
    const float* b1  = (const float*)d_in[2];
    const float* a1  = (const float*)d_in[3];
    const float* w2  = (const float*)d_in[4];
    const float* b2  = (const float*)d_in[5];
    const float* a2  = (const float*)d_in[6];
    const float* w3  = (const float*)d_in[7];
    const float* b3  = (const float*)d_in[8];
    const float* a3  = (const float*)d_in[9];
    const float* w41 = (const float*)d_in[10];
    const float* b41 = (const float*)d_in[11];
    const float* w42 = (const float*)d_in[12];
    const float* b42 = (const float*)d_in[13];
    float* out = (float*)d_out;

    const size_t SM2 = (size_t)(S2_IN + S2_W + 2*C2)*sizeof(float);
    const size_t SM3 = (size_t)(S3_IN + S3_W + 32+32+64+128+8)*sizeof(float);
    const size_t SMF = (size_t)TOPK*32*sizeof(unsigned int);
    cudaFuncSetAttribute(k_conv2,      cudaFuncAttributeMaxDynamicSharedMemorySize, (int)SM2);
    cudaFuncSetAttribute(k_conv3fused, cudaFuncAttributeMaxDynamicSharedMemorySize, (int)SM3);
    cudaFuncSetAttribute(k_final,      cudaFuncAttributeMaxDynamicSharedMemorySize, (int)SMF);

    dim3 blk(32,8);
    k_conv1pool<<<dim3((PW+31)/32,(PH+7)/8,BATCH), blk>>>(x,w1,b1,a1);
    k_conv2<<<dim3((W2+63)/64,(H2+15)/16,BATCH), blk, SM2>>>(w2,b2,a2);
    k_conv3fused<<<dim3((W3+127)/128,(H3+7)/8,BATCH), blk, SM3>>>(w3,b3,a3,w41,b41,w42,b42);
    k_reset<<<1,256>>>();
    for (int p=0;p<8;p++){
        k_hist<<<2048,256>>>(p);
        k_pick<<<1,256>>>();
    }
    k_compact<<<2048,256>>>();
    k_sort<<<1,TOPK>>>();
    k_mask<<<(TOPK*32)/256,256>>>();
    k_final<<<1,TOPK,SMF>>>(out);
}

// round 9
// speedup vs baseline: 2.3131x; 1.1694x over previous
#include <cuda_runtime.h>
#include <math.h>

#define BATCH 4
#define IN_H 1080
#define IN_W 1920
#define C1 10
#define PH 539
#define PW 959
#define C2 16
#define H2 537
#define W2 957
#define C3 32
#define H3 535
#define W3 955
#define NPIX (H3*W3)            // 510925
#define TOT (BATCH*NPIX)        // 2043700
#define TOPK 1024

// ---------------- scratch (static device memory; no allocations) ----------------
__device__ float g_pool[BATCH*C1*PH*PW];
__device__ float g_c2[BATCH*C2*H2*W2];
__device__ float g_pred[TOT*4];
__device__ unsigned long long g_keys[TOT];   // compacted valid keys [0, g_nvalid)
__device__ int g_nvalid;
__device__ unsigned int g_hist[256];
__device__ unsigned long long g_prefix;
__device__ int g_remaining;
__device__ unsigned long long g_top[TOPK];
__device__ int g_topcnt;
__device__ float4 g_boxo[TOPK];
__device__ int g_valid[TOPK];
__device__ unsigned int g_nmsmask[TOPK*32];

// ---------------- conv1 (3->10, 3x3) + PReLU + 2x2 maxpool ----------------
// Reduction order: ky -> kx -> ci (ci innermost), FMA chain, bias added at END.
__global__ __launch_bounds__(256,2) void k_conv1pool(
    const float* __restrict__ x, const float* __restrict__ w,
    const float* __restrict__ bias, const float* __restrict__ alpha)
{
    __shared__ __align__(16) float s_in[3*18*66];
    __shared__ __align__(16) float s_w[27*12];
    __shared__ float s_b[C1], s_a[C1];
    const int tx = threadIdx.x, ty = threadIdx.y;
    const int tid = ty*32 + tx;
    const int b = blockIdx.z;
    const int px0 = blockIdx.x*32, py0 = blockIdx.y*8;
    const int ix0 = px0*2, iy0 = py0*2;

    for (int i = tid; i < 270; i += 256) {
        int st = i/10, co = i%10;
        int ci = st % 3; int r = st / 3; int ky = r/3, kx = r%3;
        s_w[st*12+co] = w[co*27 + ci*9 + ky*3 + kx];
    }
    if (tid < C1) { s_b[tid]=bias[tid]; s_a[tid]=alpha[tid]; }
    for (int i = tid; i < 3*18*66; i += 256) {
        int c = i/(18*66); int r = (i/66)%18; int cc = i%66;
        int gy = iy0 + r, gx = ix0 + cc;
        float v = 0.f;
        if (gy < IN_H && gx < IN_W) v = x[((b*3 + c)*IN_H + gy)*IN_W + gx];
        s_in[i] = v;
    }
    __syncthreads();
    const int px = px0 + tx, py = py0 + ty;
    if (px >= PW || py >= PH) return;

    float acc[4][C1];
    #pragma unroll
    for (int p=0;p<4;p++)
      #pragma unroll
      for (int co=0;co<C1;co++) acc[p][co] = 0.f;

    #pragma unroll
    for (int ky=0;ky<3;ky++){
      #pragma unroll
      for (int kx=0;kx<3;kx++){
        #pragma unroll
        for (int ci=0;ci<3;ci++){
          const int st = (ky*3+kx)*3+ci;
          const float4 wa = *(const float4*)&s_w[st*12];
          const float4 wb = *(const float4*)&s_w[st*12+4];
          const float2 wc = *(const float2*)&s_w[st*12+8];
          const float wv[10] = {wa.x,wa.y,wa.z,wa.w, wb.x,wb.y,wb.z,wb.w, wc.x,wc.y};
          float v[4];
          #pragma unroll
          for (int pyi=0;pyi<2;pyi++)
            #pragma unroll
            for (int pxi=0;pxi<2;pxi++)
              v[pyi*2+pxi] = s_in[ci*(18*66) + (2*ty+pyi+ky)*66 + (2*tx+pxi+kx)];
          #pragma unroll
          for (int p=0;p<4;p++)
            #pragma unroll
            for (int co=0;co<C1;co++)
              acc[p][co] = __fmaf_rn(v[p], wv[co], acc[p][co]);
        }
      }
    }
    #pragma unroll
    for (int co=0;co<C1;co++){
      float m = -1e30f;
      #pragma unroll
      for (int p=0;p<4;p++){
        float t = acc[p][co] + s_b[co];
        t = (t >= 0.f) ? t : s_a[co]*t;
        m = fmaxf(m, t);
      }
      g_pool[((b*C1+co)*PH+py)*PW+px] = m;
    }
}

// ---------------- conv2 (10->16, 3x3) + PReLU ----------------
#define S2_IN (10*18*66)   // 11880
#define S2_W  (90*16)      // 1440
__global__ __launch_bounds__(256,2) void k_conv2(
    const float* __restrict__ w, const float* __restrict__ bias, const float* __restrict__ alpha)
{
    extern __shared__ float sm2[];
    float* s_in = sm2;
    float* s_w  = sm2 + S2_IN;
    float* s_b  = s_w + S2_W;
    float* s_a  = s_b + C2;
    const int tx = threadIdx.x, ty = threadIdx.y;
    const int tid = ty*32+tx;
    const int b = blockIdx.z;
    const int ox0 = blockIdx.x*64, oy0 = blockIdx.y*16;

    for (int i = tid; i < S2_W; i += 256){
        int st=i/16, co=i%16;
        int ci = st % 10; int r = st / 10; int ky = r/3, kx = r%3;
        s_w[i] = w[co*90 + ci*9 + ky*3 + kx];
    }
    if (tid < C2){ s_b[tid]=bias[tid]; s_a[tid]=alpha[tid]; }
    for (int i = tid; i < S2_IN; i += 256){
        int ci = i/(18*66); int r=(i/66)%18; int cc=i%66;
        int gy=oy0+r, gx=ox0+cc;
        float v=0.f;
        if (gy<PH && gx<PW) v = g_pool[((b*C1+ci)*PH+gy)*PW+gx];
        s_in[i]=v;
    }
    __syncthreads();

    float acc[4][C2];
    #pragma unroll
    for (int p=0;p<4;p++)
      #pragma unroll
      for (int co=0;co<C2;co++) acc[p][co]=0.f;

    #pragma unroll
    for (int ky=0;ky<3;ky++){
      #pragma unroll
      for (int kx=0;kx<3;kx++){
        #pragma unroll 1
        for (int ci=0;ci<C1;ci++){
          const int st = (ky*3+kx)*10+ci;
          const float4 w0 = *(const float4*)&s_w[st*16];
          const float4 w1 = *(const float4*)&s_w[st*16+4];
          const float4 w2 = *(const float4*)&s_w[st*16+8];
          const float4 w3 = *(const float4*)&s_w[st*16+12];
          const float wv[16] = {w0.x,w0.y,w0.z,w0.w, w1.x,w1.y,w1.z,w1.w,
                                w2.x,w2.y,w2.z,w2.w, w3.x,w3.y,w3.z,w3.w};
          float v[4];
          #pragma unroll
          for (int pyi=0;pyi<2;pyi++)
            #pragma unroll
            for (int pxi=0;pxi<2;pxi++)
              v[pyi*2+pxi] = s_in[ci*(18*66) + (ty+8*pyi+ky)*66 + (tx+32*pxi+kx)];
          #pragma unroll
          for (int p=0;p<4;p++)
            #pragma unroll
            for (int co=0;co<C2;co++)
              acc[p][co] = __fmaf_rn(v[p], wv[co], acc[p][co]);
        }
      }
    }
    #pragma unroll
    for (int pyi=0;pyi<2;pyi++){
      int oy = oy0 + ty + 8*pyi;
      #pragma unroll
      for (int pxi=0;pxi<2;pxi++){
        int ox = ox0 + tx + 32*pxi;
        if (oy < H2 && ox < W2){
          int p = pyi*2+pxi;
          #pragma unroll
          for (int co=0;co<C2;co++){
            float t = acc[p][co] + s_b[co];
            t = (t>=0.f) ? t : s_a[co]*t;
            g_c2[((b*C2+co)*H2+oy)*W2+ox] = t;
          }
        }
      }
    }
}

// ------- conv3 (16->32, 3x3) + PReLU + 1x1 heads + softmax + compact key emit -------
#define S3_IN (16*10*66)   // 10560
#define S3_W  (144*32)     // 4608
__global__ __launch_bounds__(256,1) void k_conv3fused(
    const float* __restrict__ w3, const float* __restrict__ b3, const float* __restrict__ a3,
    const float* __restrict__ w41, const float* __restrict__ b41,
    const float* __restrict__ w42, const float* __restrict__ b42)
{
    extern __shared__ float sm3[];
    float* s_in  = sm3;
    float* s_w   = sm3 + S3_IN;
    float* s_b   = s_w + S3_W;     // 32
    float* s_a   = s_b + 32;       // 32
    float* s_w41 = s_a + 32;       // 64
    float* s_w42 = s_w41 + 64;     // 128
    float* s_b4  = s_w42 + 128;    // 8
    const int tx=threadIdx.x, ty=threadIdx.y, tid=ty*32+tx;
    const int b = blockIdx.z;
    const int ox0 = blockIdx.x*64, oy0 = blockIdx.y*8;

    for (int i=tid;i<S3_W;i+=256){
        int st=i/32, co=i%32;
        int ci = st % 16; int r = st / 16; int ky = r/3, kx = r%3;
        s_w[i] = w3[co*144 + ci*9 + ky*3 + kx];
    }
    if (tid<32){ s_b[tid]=b3[tid]; s_a[tid]=a3[tid]; }
    if (tid<64)  s_w41[tid]=w41[tid];
    if (tid<128) s_w42[tid]=w42[tid];
    if (tid<2)   s_b4[tid]=b41[tid];
    if (tid>=4 && tid<8) s_b4[tid-2]=b42[tid-4];
    for (int i=tid;i<S3_IN;i+=256){
        int ci=i/(10*66); int r=(i/66)%10; int cc=i%66;
        int gy=oy0+r, gx=ox0+cc;
        float v=0.f;
        if (gy<H2 && gx<W2) v = g_c2[((b*C2+ci)*H2+gy)*W2+gx];
        s_in[i]=v;
    }
    __syncthreads();

    float acc[2][C3];
    #pragma unroll
    for (int co=0;co<C3;co++){ acc[0][co]=0.f; acc[1][co]=0.f; }

    #pragma unroll
    for (int ky=0;ky<3;ky++){
      #pragma unroll
      for (int kx=0;kx<3;kx++){
        #pragma unroll 1
        for (int ci=0;ci<16;ci++){
          const int st = (ky*3+kx)*16+ci;
          float wv[32];
          #pragma unroll
          for (int q=0;q<8;q++){
            float4 t4 = *(const float4*)&s_w[st*32 + q*4];
            wv[q*4]=t4.x; wv[q*4+1]=t4.y; wv[q*4+2]=t4.z; wv[q*4+3]=t4.w;
          }
          const float v0 = s_in[ci*660 + (ty+ky)*66 + (tx+kx)];
          const float v1 = s_in[ci*660 + (ty+ky)*66 + (tx+32+kx)];
          #pragma unroll
          for (int co=0;co<32;co++){
            acc[0][co] = __fmaf_rn(v0, wv[co], acc[0][co]);
            acc[1][co] = __fmaf_rn(v1, wv[co], acc[1][co]);
          }
        }
      }
    }

    const int oy = oy0 + ty;
    const bool rowok = (oy < H3);
    #pragma unroll
    for (int p=0;p<2;p++){
      const int ox = ox0 + tx + 32*p;
      const bool inb = rowok && (ox < W3);
      unsigned long long key = 0ULL;
      bool has = false;
      if (inb){
        float l0 = 0.f, l1 = 0.f;
        float pr0=0.f, pr1=0.f, pr2=0.f, pr3=0.f;
        #pragma unroll
        for (int co=0;co<32;co++){
          float h = acc[p][co] + s_b[co];
          h = (h>=0.f) ? h : s_a[co]*h;
          l0  = __fmaf_rn(h, s_w41[co],     l0);
          l1  = __fmaf_rn(h, s_w41[32+co],  l1);
          pr0 = __fmaf_rn(h, s_w42[co],     pr0);
          pr1 = __fmaf_rn(h, s_w42[32+co],  pr1);
          pr2 = __fmaf_rn(h, s_w42[64+co],  pr2);
          pr3 = __fmaf_rn(h, s_w42[96+co],  pr3);
        }
        l0 += s_b4[0]; l1 += s_b4[1];
        pr0 += s_b4[2]; pr1 += s_b4[3]; pr2 += s_b4[4]; pr3 += s_b4[5];
        float m  = fmaxf(l0,l1);
        float e0 = expf(l0-m), e1 = expf(l1-m);
        float score = __fdiv_rn(e1, __fadd_rn(e0,e1));
        int gidx = b*NPIX + oy*W3 + ox;
        g_pred[gidx*4+0]=pr0; g_pred[gidx*4+1]=pr1; g_pred[gidx*4+2]=pr2; g_pred[gidx*4+3]=pr3;
        if (score >= 0.6f){
          unsigned u = __float_as_uint(score) | 0x80000000u;   // byte0 always 0xBF
          key = ((unsigned long long)u << 32) | (unsigned long long)(0xFFFFFFFFu - (unsigned)gidx);
          has = true;
        }
      }
      // warp-aggregated append of valid keys
      unsigned mask = __ballot_sync(0xffffffffu, has);
      if (mask){
        int leader = __ffs(mask)-1;
        unsigned basepos = 0;
        if (tx == leader) basepos = (unsigned)atomicAdd(&g_nvalid, __popc(mask));
        basepos = __shfl_sync(0xffffffffu, basepos, leader);
        if (has){
          int off = __popc(mask & ((1u<<tx)-1u));
          g_keys[basepos+off] = key;
        }
      }
    }
}

// ---------------- exact top-K over compacted valid keys ----------------
// All valid keys have byte0 = 0xBF (score in [0.6,1]) and byte4 = 0xFF (gidx < 2^21),
// so those two radix passes are constant and skipped analytically.
__global__ void k_reset(){       // BEFORE convs: zero hist, g_top, nvalid
    int t = blockIdx.x*blockDim.x + threadIdx.x;
    if (t < 256)  g_hist[t]=0u;
    if (t < TOPK) g_top[t]=0ULL;
    if (t == 0)   g_nvalid = 0;
}

__global__ void k_start(){       // AFTER conv3
    int nv = g_nvalid;
    g_remaining = nv < TOPK ? nv : TOPK;
    g_prefix = 0xBFULL;          // byte0 of every valid key
    g_topcnt = 0;
}

__global__ void k_skip(){        // inject constant byte4 = 0xFF
    g_prefix = (g_prefix<<8) | 0xFFULL;
}

__global__ void k_hist(int p){   // p in {1,2,3,5,6,7}
    __shared__ unsigned int sh[256];
    int t = threadIdx.x;
    sh[t]=0u; __syncthreads();
    unsigned long long pref = g_prefix;
    int n = g_nvalid;
    int shd = 56 - 8*p;
    for (int i = blockIdx.x*blockDim.x + t; i < n; i += gridDim.x*blockDim.x){
        unsigned long long key = g_keys[i];
        if ((key >> (64-8*p)) == pref) atomicAdd(&sh[(unsigned)(key>>shd)&255u], 1u);
    }
    __syncthreads();
    if (sh[t]) atomicAdd(&g_hist[t], sh[t]);
}

__global__ void k_pick(){
    __shared__ unsigned int sh[256];
    int t = threadIdx.x;
    sh[t] = g_hist[t];
    __syncthreads();
    if (t == 0){
        int r = g_remaining;
        unsigned c = 0;
        for (int d=255; d>=0; d--){
            unsigned h = sh[d];
            if (c + h >= (unsigned)r){
                g_prefix = (g_prefix<<8) | (unsigned long long)d;
                g_remaining = r - (int)c;
                break;
            }
            c += h;
        }
    }
    g_hist[t] = 0u;
}

__global__ void k_compact(){
    unsigned long long T = g_prefix;   // exact r-th-largest valid key
    int n = g_nvalid;
    for (int i = blockIdx.x*blockDim.x + threadIdx.x; i < n; i += gridDim.x*blockDim.x){
        unsigned long long key = g_keys[i];
        if (key >= T){
            int pos = atomicAdd(&g_topcnt, 1);
            if (pos < TOPK) g_top[pos] = key;
        }
    }
}

// ---------------- bitonic sort (desc) + box decode ----------------
__global__ void k_sort(){
    __shared__ unsigned long long sk[TOPK];
    int t = threadIdx.x;
    sk[t] = g_top[t];
    for (int size=2; size<=TOPK; size<<=1){
      for (int stride=size>>1; stride>0; stride>>=1){
        __syncthreads();
        int j = t ^ stride;
        if (j > t){
          unsigned long long a = sk[t], c = sk[j];
          bool desc = ((t & size) == 0);
          bool sw = desc ? (a < c) : (a > c);
          if (sw){ sk[t]=c; sk[j]=a; }
        }
      }
    }
    __syncthreads();
    unsigned long long key = sk[t];
    g_top[t] = key;
    int valid = (key >> 32) != 0ULL;
    int idx = valid ? (int)(0xFFFFFFFFu - (unsigned)(key & 0xFFFFFFFFULL)) : 0;
    int bb = idx / NPIX; int rem = idx - bb*NPIX;
    int oy = rem / W3;   int ox = rem - oy*W3;
    float off = valid ? 100000.f * (float)bb : 0.f;
    float4 box;
    box.x = (float)(2*ox+1)  + off;
    box.y = (float)(2*oy+1)  + off;
    box.z = (float)(2*ox+12) + off;
    box.w = (float)(2*oy+12) + off;
    g_boxo[t]  = box;
    g_valid[t] = valid;
}

// ---------------- pairwise suppression bits ----------------
__global__ void k_mask(){
    int tid = blockIdx.x*blockDim.x + threadIdx.x;
    int i = tid >> 5;
    int w = tid & 31;
    if (i >= TOPK) return;
    float4 bi = g_boxo[i];
    float ai = (bi.z-bi.x)*(bi.w-bi.y);
    unsigned m = 0u;
    #pragma unroll 4
    for (int t2=0;t2<32;t2++){
        int j = w*32 + t2;
        float4 bj = g_boxo[j];
        float aj = (bj.z-bj.x)*(bj.w-bj.y);
        float xx1=fmaxf(bi.x,bj.x), yy1=fmaxf(bi.y,bj.y);
        float xx2=fminf(bi.z,bj.z), yy2=fminf(bi.w,bj.w);
        float inter = fmaxf(xx2-xx1,0.f)*fmaxf(yy2-yy1,0.f);
        float iou = __fdiv_rn(inter, ai+aj-inter);
        if (j > i && iou > 0.5f) m |= (1u<<t2);
    }
    g_nmsmask[i*32+w] = m;
}

// ---------------- sequential greedy NMS + refine + output ----------------
__global__ void k_final(float* __restrict__ out){
    extern __shared__ unsigned int smm[];     // TOPK*32 words
    __shared__ unsigned int s_keepw[32];
    int t = threadIdx.x;
    for (int i=t; i<TOPK*32; i+=TOPK) smm[i] = g_nmsmask[i];
    __syncthreads();
    if (t < 32){
        unsigned vword = 0u;
        for (int q=0;q<32;q++) vword |= (g_valid[t*32+q] ? 1u:0u) << q;
        unsigned sup = 0u, keepw = 0u;
        for (int i=0;i<TOPK;i++){
            int l = i >> 5, bb = i & 31;
            unsigned sw = __shfl_sync(0xffffffffu, sup,   l);
            unsigned vw = __shfl_sync(0xffffffffu, vword, l);
            bool keep = !((sw >> bb) & 1u) && ((vw >> bb) & 1u);
            if (keep) sup |= smm[i*32 + t];
            if (t == l) keepw |= ((unsigned)keep) << bb;
        }
        s_keepw[t] = keepw;
    }
    __syncthreads();
    bool keep = (s_keepw[t>>5] >> (t&31)) & 1u;
    float o0=0.f,o1=0.f,o2=0.f,o3=0.f,o4=0.f;
    if (keep){
        unsigned long long key = g_top[t];
        unsigned u = (unsigned)(key>>32);
        float score = __uint_as_float(u & 0x7FFFFFFFu);
        int idx = (int)(0xFFFFFFFFu - (unsigned)(key & 0xFFFFFFFFULL));
        int rem = idx % NPIX;
        int oy = rem / W3; int ox = rem - oy*W3;
        float x1 = (float)(2*ox+1),  y1 = (float)(2*oy+1);
        float x2 = (float)(2*ox+12), y2 = (float)(2*oy+12);
        float bw = x2-x1, bh = y2-y1;
        float p0 = g_pred[idx*4+0], p1=g_pred[idx*4+1], p2=g_pred[idx*4+2], p3=g_pred[idx*4+3];
        float r0 = x1 + p0*bw;
        float r1 = y1 + p1*bh;
        float r2 = x2 + p2*bw;
        float r3 = y2 + p3*bh;
        float rw = r2-r0, rh = r3-r1;
        float L = fmaxf(rw, rh);
        float nx1 = r0 + 0.5f*rw - 0.5f*L;
        float ny1 = r1 + 0.5f*rh - 0.5f*L;
        o0=nx1; o1=ny1; o2=nx1+L; o3=ny1+L; o4=score;
    }
    out[t*5+0]=o0; out[t*5+1]=o1; out[t*5+2]=o2; out[t*5+3]=o3; out[t*5+4]=o4;
}

// ---------------- launch ----------------
extern "C" void kernel_launch(void* const* d_in, const int* in_sizes, int n_in,
                              void* d_out, int out_size){
    const float* x   = (const float*)d_in[0];
    const float* w1  = (const float*)d_in[1];
    const float* b1  = (const float*)d_in[2];
    const float* a1  = (const float*)d_in[3];
    const float* w2  = (const float*)d_in[4];
    const float* b2  = (const float*)d_in[5];
    const float* a2  = (const float*)d_in[6];
    const float* w3  = (const float*)d_in[7];
    const float* b3  = (const float*)d_in[8];
    const float* a3  = (const float*)d_in[9];
    const float* w41 = (const float*)d_in[10];
    const float* b41 = (const float*)d_in[11];
    const float* w42 = (const float*)d_in[12];
    const float* b42 = (const float*)d_in[13];
    float* out = (float*)d_out;

    const size_t SM2 = (size_t)(S2_IN + S2_W + 2*C2)*sizeof(float);
    const size_t SM3 = (size_t)(S3_IN + S3_W + 32+32+64+128+8)*sizeof(float);
    const size_t SMF = (size_t)TOPK*32*sizeof(unsigned int);
    cudaFuncSetAttribute(k_conv2,      cudaFuncAttributeMaxDynamicSharedMemorySize, (int)SM2);
    cudaFuncSetAttribute(k_conv3fused, cudaFuncAttributeMaxDynamicSharedMemorySize, (int)SM3);
    cudaFuncSetAttribute(k_final,      cudaFuncAttributeMaxDynamicSharedMemorySize, (int)SMF);

    dim3 blk(32,8);
    k_reset<<<4,256>>>();
    k_conv1pool<<<dim3((PW+31)/32,(PH+7)/8,BATCH), blk>>>(x,w1,b1,a1);
    k_conv2<<<dim3((W2+63)/64,(H2+15)/16,BATCH), blk, SM2>>>(w2,b2,a2);
    k_conv3fused<<<dim3((W3+63)/64,(H3+7)/8,BATCH), blk, SM3>>>(w3,b3,a3,w41,b41,w42,b42);
    k_start<<<1,1>>>();
    const int passes[6] = {1,2,3,5,6,7};
    for (int q=0;q<6;q++){
        if (q == 3) k_skip<<<1,1>>>();     // byte4 == 0xFF for all valid keys
        k_hist<<<1024,256>>>(passes[q]);
        k_pick<<<1,256>>>();
    }
    k_compact<<<1024,256>>>();
    k_sort<<<1,TOPK>>>();
    k_mask<<<(TOPK*32)/256,256>>>();
    k_final<<<1,TOPK,SMF>>>(out);
}